// round 4
// baseline (speedup 1.0000x reference)
#include <cuda_runtime.h>
#include <math.h>

constexpr int B_    = 512;
constexpr int LEN_  = 1000;
constexpr int D_    = 16;
constexpr int HID_  = 256;
constexpr int WIN_  = 64;
constexpr int PAIRS_  = 120;
constexpr int LOGSIG_ = 136;
constexpr int K1_   = HID_ + LOGSIG_;   // 392
constexpr int K1P_  = 416;              // 13*32

__device__ float g_X[(size_t)B_ * LEN_ * D_];
__device__ float g_ls[(size_t)WIN_ * B_ * LOGSIG_];
__device__ float g_last[2][(size_t)B_ * HID_];
__device__ float g_dts[LEN_ - 1];
__device__ int   g_tidx[WIN_ - 1];
__device__ int   g_sidx[WIN_ - 1];
__device__ int   g_iu[PAIRS_];
__device__ int   g_ju[PAIRS_];

__host__ __device__ __forceinline__ double tb_d(int i) {
    return (i == LEN_ - 1) ? 1.0 : (double)i * (1.0 / 999.0);
}
__host__ __device__ __forceinline__ double tt_d(int k) {
    return (k == WIN_ - 1) ? 1.0 : (double)k * (1.0 / 63.0);
}

__global__ void sched_kernel() {
    int tid = threadIdx.x;
    for (int i = tid; i < LEN_ - 1; i += blockDim.x)
        g_dts[i] = sqrtf((float)(tb_d(i + 1) - tb_d(i)));
    if (tid < WIN_ - 1) {
        double t = tt_d(tid + 1);
        int ti = 0;
        for (int i = 0; i < LEN_; i++) if (tb_d(i) <= t) ti = i;
        g_tidx[tid] = ti;
        int uj = 0;
        for (int j = 0; j < LEN_ / 50; j++) if (tb_d(50 * j) <= t) uj = j;
        g_sidx[tid] = 50 * uj;
    }
    if (tid >= 64 && tid < 64 + PAIRS_) {
        int p = tid - 64;
        int i = 0, accp = 0;
        while (accp + (D_ - 1 - i) <= p) { accp += D_ - 1 - i; i++; }
        g_iu[p] = i;
        g_ju[p] = i + 1 + (p - accp);
    }
}

__global__ void zero_last_kernel() {
    int g = blockIdx.x * blockDim.x + threadIdx.x;
    if (g < B_ * HID_) g_last[0][g] = 0.f;
}

__global__ void cumsum_kernel(const float* __restrict__ z) {
    int g = blockIdx.x * blockDim.x + threadIdx.x;   // B*D = 8192
    int b = g >> 4, d = g & 15;
    const float* zp = z + (size_t)b * LEN_ * D_ + d;
    float* xp = g_X + (size_t)b * LEN_ * D_ + d;
    float acc = 0.f;
    xp[0] = 0.f;
    #pragma unroll 8
    for (int t = 1; t < LEN_; t++) {
        acc += zp[(size_t)t * D_] * g_dts[t - 1];
        xp[(size_t)t * D_] = acc;
    }
}

__global__ void logsig_kernel() {
    int kk = blockIdx.x, b = blockIdx.y, tid = threadIdx.x;
    if (kk == 0) {
        if (tid < LOGSIG_) g_ls[(size_t)b * LOGSIG_ + tid] = 0.f;
        return;
    }
    int k = kk - 1, t1 = g_tidx[k], s0 = g_sidx[k];
    int nrow = t1 - s0 + 1;                          // <= 50
    __shared__ float sX[50 * 16];
    const float* xb = g_X + ((size_t)b * LEN_ + s0) * D_;
    for (int e = tid; e < nrow * D_; e += blockDim.x) sX[e] = xb[e];
    __syncthreads();
    float* outp = g_ls + ((size_t)kk * B_ + b) * LOGSIG_;
    if (tid < D_) {
        outp[tid] = sX[(t1 - s0) * D_ + tid];
    } else if (tid < LOGSIG_) {
        int p = tid - D_, iu = g_iu[p], ju = g_ju[p];
        float acc = 0.f;
        for (int s = 0; s < nrow - 1; s++) {
            float xi = sX[s * D_ + iu],       xj = sX[s * D_ + ju];
            float yi = sX[(s + 1) * D_ + iu], yj = sX[(s + 1) * D_ + ju];
            acc += xi * (yj - xj) - xj * (yi - xi);
        }
        outp[tid] = 0.5f * acc;
    }
}

// GEMM over smem input: thread computes outputs {jg, jg+128} for RT rows.
template<int RT>
__device__ __forceinline__ void gemm_smem(
    const float* __restrict__ Wg, const float* __restrict__ sin,
    int sstride, int K, float* __restrict__ sW,
    int tid, int jg, int r0, float acc[2][RT])
{
    #pragma unroll
    for (int q = 0; q < 2; q++)
        #pragma unroll
        for (int rr = 0; rr < RT; rr++) acc[q][rr] = 0.f;
    const int nch = (K + 31) >> 5;
    for (int ch = 0; ch < nch; ch++) {
        const int k0 = ch << 5;
        __syncthreads();
        #pragma unroll
        for (int u = 0; u < 8; u++) {
            int g = (u << 8) + tid;
            int row = g >> 3;
            int k = k0 + ((g & 7) << 2);
            float4 v;
            if (k + 4 <= K) {
                v = *reinterpret_cast<const float4*>(Wg + (size_t)row * K + k);
            } else {
                v.x = (k + 0 < K) ? Wg[(size_t)row * K + k + 0] : 0.f;
                v.y = (k + 1 < K) ? Wg[(size_t)row * K + k + 1] : 0.f;
                v.z = (k + 2 < K) ? Wg[(size_t)row * K + k + 2] : 0.f;
                v.w = (k + 3 < K) ? Wg[(size_t)row * K + k + 3] : 0.f;
            }
            *reinterpret_cast<float4*>(sW + row * 36 + ((g & 7) << 2)) = v;
        }
        __syncthreads();
        #pragma unroll
        for (int cg = 0; cg < 8; cg++) {
            float4 w0 = *reinterpret_cast<const float4*>(sW + jg * 36 + (cg << 2));
            float4 w1 = *reinterpret_cast<const float4*>(sW + (jg + 128) * 36 + (cg << 2));
            #pragma unroll
            for (int rr = 0; rr < RT; rr++) {
                float4 x = *reinterpret_cast<const float4*>(
                    sin + (r0 + rr) * sstride + k0 + (cg << 2));
                acc[0][rr] = fmaf(w0.x, x.x, fmaf(w0.y, x.y,
                              fmaf(w0.z, x.z, fmaf(w0.w, x.w, acc[0][rr]))));
                acc[1][rr] = fmaf(w1.x, x.x, fmaf(w1.y, x.y,
                              fmaf(w1.z, x.z, fmaf(w1.w, x.w, acc[1][rr]))));
            }
        }
    }
}

// One launch handles one constant-last_h segment; CTA = 8 rows, full 4-layer MLP.
template<int BT>
__global__ void __launch_bounds__(256)
rnn_round_kernel(const float* __restrict__ W1, const float* __restrict__ b1,
                 const float* __restrict__ W2, const float* __restrict__ b2,
                 const float* __restrict__ W3, const float* __restrict__ b3,
                 const float* __restrict__ Wl, float* __restrict__ out,
                 int parity, int step0, int seglen)
{
    constexpr int RT = BT / 2;
    extern __shared__ float smem[];
    float* sW  = smem;                      // 256*36
    float* sIn = sW + 256 * 36;             // BT*416 (reused as h)
    float* sA  = sIn + BT * K1P_;           // BT*256
    float* sB  = sA + BT * HID_;            // BT*256

    const float* last_in  = g_last[parity];
    float*       last_out = g_last[parity ^ 1];

    const int tid = threadIdx.x;
    const int jg  = tid & 127;
    const int r0  = (tid >> 7) * RT;
    const int base = blockIdx.x * BT;
    const int step = step0 + (base >> 9);
    const int b0   = base & 511;
    const bool is_last = (step == step0 + seglen - 1);

    for (int r = 0; r < BT; r++) {
        int b = b0 + r;
        for (int c = tid; c < K1P_; c += 256) {
            float v = 0.f;
            if (c < HID_)     v = last_in[(size_t)b * HID_ + c];
            else if (c < K1_) v = g_ls[((size_t)step * B_ + b) * LOGSIG_ + (c - HID_)];
            sIn[r * K1P_ + c] = v;
        }
    }

    float acc[2][RT];

    gemm_smem<RT>(W1, sIn, K1P_, K1_, sW, tid, jg, r0, acc);
    #pragma unroll
    for (int q = 0; q < 2; q++) {
        int j = jg + (q << 7); float bb = b1[j];
        #pragma unroll
        for (int rr = 0; rr < RT; rr++)
            sA[(r0 + rr) * HID_ + j] = fmaxf(acc[q][rr] + bb, 0.f);
    }

    gemm_smem<RT>(W2, sA, HID_, HID_, sW, tid, jg, r0, acc);
    #pragma unroll
    for (int q = 0; q < 2; q++) {
        int j = jg + (q << 7); float bb = b2[j];
        #pragma unroll
        for (int rr = 0; rr < RT; rr++)
            sB[(r0 + rr) * HID_ + j] = fmaxf(acc[q][rr] + bb, 0.f);
    }

    float* sH = sIn;
    gemm_smem<RT>(W3, sB, HID_, HID_, sW, tid, jg, r0, acc);
    #pragma unroll
    for (int q = 0; q < 2; q++) {
        int j = jg + (q << 7); float bb = b3[j];
        #pragma unroll
        for (int rr = 0; rr < RT; rr++) {
            float h = tanhf(acc[q][rr] + bb);
            sH[(r0 + rr) * HID_ + j] = h;
            if (is_last) last_out[(size_t)(b0 + r0 + rr) * HID_ + j] = h;
        }
    }

    gemm_smem<RT>(Wl, sH, HID_, HID_, sW, tid, jg, r0, acc);
    #pragma unroll
    for (int q = 0; q < 2; q++) {
        int j = jg + (q << 7);
        #pragma unroll
        for (int rr = 0; rr < RT; rr++) {
            int b = b0 + r0 + rr;
            out[((size_t)b * WIN_ + step) * HID_ + j] = acc[q][rr];
        }
    }
}

// Replicate the reference's upd schedule -> segments (exact double math).
static void host_segments(int* seg_start, int* seg_len, int* nseg) {
    double tu[20];
    for (int j = 0; j < 20; j++) tu[j] = tb_d(50 * j);
    int u_idx[63];
    for (int k = 1; k < 64; k++) {
        double t = tt_d(k);
        int uj = 0;
        for (int j = 0; j < 20; j++) if (tu[j] <= t) uj = j;
        u_idx[k - 1] = uj;
    }
    double qt[64]; int qn = 0, last = -1;
    for (int k = 0; k < 63; k++) {
        int iu = u_idx[k] < 0 ? 0 : u_idx[k];
        if (iu != last) { qt[qn++] = tu[iu]; last = iu; }
    }
    qt[qn++] = tt_d(63);
    bool upd[64]; int qh = 0;
    for (int i = 0; i < 64; i++) {
        upd[i] = false;
        if (qh < qn && tt_d(i) >= qt[qh]) { qh++; upd[i] = true; }
    }
    *nseg = 0; int start = 0;
    for (int i = 0; i < 64; i++) {
        if (upd[i]) { seg_start[*nseg] = start; seg_len[*nseg] = i - start + 1; (*nseg)++; start = i + 1; }
    }
    if (start < 64) { seg_start[*nseg] = start; seg_len[*nseg] = 64 - start; (*nseg)++; }
}

extern "C" void kernel_launch(void* const* d_in, const int* in_sizes, int n_in,
                              void* d_out, int out_size) {
    (void)in_sizes; (void)n_in; (void)out_size;
    const float* z  = (const float*)d_in[0];
    const float* W1 = (const float*)d_in[1];
    const float* b1 = (const float*)d_in[2];
    const float* W2 = (const float*)d_in[3];
    const float* b2 = (const float*)d_in[4];
    const float* W3 = (const float*)d_in[5];
    const float* b3 = (const float*)d_in[6];
    const float* Wl = (const float*)d_in[7];
    float* out = (float*)d_out;

    constexpr int BT = 8;
    const size_t smem_bytes = (256 * 36 + BT * K1P_ + 2 * BT * HID_) * sizeof(float);
    static bool attr_done = false;
    if (!attr_done) {
        cudaFuncSetAttribute(rnn_round_kernel<BT>,
                             cudaFuncAttributeMaxDynamicSharedMemorySize,
                             (int)smem_bytes);
        attr_done = true;
    }

    sched_kernel<<<1, 256>>>();
    zero_last_kernel<<<(B_ * HID_ + 255) / 256, 256>>>();
    cumsum_kernel<<<(B_ * D_) / 256, 256>>>(z);
    logsig_kernel<<<dim3(WIN_, B_), 160>>>();

    int seg_start[64], seg_len[64], nseg = 0;
    host_segments(seg_start, seg_len, &nseg);

    int parity = 0;
    for (int s = 0; s < nseg; s++) {
        int grid = seg_len[s] * (B_ / BT);
        rnn_round_kernel<BT><<<grid, 256, smem_bytes>>>(
            W1, b1, W2, b2, W3, b3, Wl, out, parity, seg_start[s], seg_len[s]);
        parity ^= 1;
    }
}

// round 5
// speedup vs baseline: 1.1354x; 1.1354x over previous
#include <cuda_runtime.h>
#include <math.h>
#include <stdint.h>

constexpr int B_    = 512;
constexpr int LEN_  = 1000;
constexpr int D_    = 16;
constexpr int HID_  = 256;
constexpr int WIN_  = 64;
constexpr int PAIRS_  = 120;
constexpr int LOGSIG_ = 136;
constexpr int K1_   = HID_ + LOGSIG_;   // 392
constexpr int K1P_  = 416;              // 13*32
constexpr int BT_   = 8;                // batch rows per CTA
constexpr int NCHUNK_ = 8;              // cumsum time chunks
constexpr int WTILE_ = 256 * 36;        // padded W tile floats

__device__ float g_X[(size_t)B_ * LEN_ * D_];
__device__ float g_ls[(size_t)WIN_ * B_ * LOGSIG_];
__device__ float g_last[2][(size_t)B_ * HID_];
__device__ float g_part[(size_t)B_ * NCHUNK_ * D_];
__device__ float g_dts[LEN_ - 1];
__device__ int   g_tidx[WIN_ - 1];
__device__ int   g_sidx[WIN_ - 1];
__device__ int   g_iu[PAIRS_];
__device__ int   g_ju[PAIRS_];

__host__ __device__ __forceinline__ double tb_d(int i) {
    return (i == LEN_ - 1) ? 1.0 : (double)i * (1.0 / 999.0);
}
__host__ __device__ __forceinline__ double tt_d(int k) {
    return (k == WIN_ - 1) ? 1.0 : (double)k * (1.0 / 63.0);
}

__global__ void sched_kernel() {
    int tid = threadIdx.x;
    for (int i = tid; i < LEN_ - 1; i += blockDim.x)
        g_dts[i] = sqrtf((float)(tb_d(i + 1) - tb_d(i)));
    if (tid < WIN_ - 1) {
        double t = tt_d(tid + 1);
        int ti = 0;
        for (int i = 0; i < LEN_; i++) if (tb_d(i) <= t) ti = i;
        g_tidx[tid] = ti;
        int uj = 0;
        for (int j = 0; j < LEN_ / 50; j++) if (tb_d(50 * j) <= t) uj = j;
        g_sidx[tid] = 50 * uj;
    }
    if (tid >= 64 && tid < 64 + PAIRS_) {
        int p = tid - 64;
        int i = 0, accp = 0;
        while (accp + (D_ - 1 - i) <= p) { accp += D_ - 1 - i; i++; }
        g_iu[p] = i;
        g_ju[p] = i + 1 + (p - accp);
    }
}

__global__ void zero_last_kernel() {
    int g = blockIdx.x * blockDim.x + threadIdx.x;
    if (g < B_ * HID_) g_last[0][g] = 0.f;
}

// ---- chunked cumsum: phase 1 partial sums ----
__global__ void cumsum_part_kernel(const float* __restrict__ z) {
    int g = blockIdx.x * blockDim.x + threadIdx.x;   // B*NCHUNK*D = 65536
    int d = g & 15, c = (g >> 4) & (NCHUNK_ - 1), b = g >> 7;
    int t0 = c * 125 + 1;
    int t1 = (c + 1) * 125; if (t1 > LEN_ - 1) t1 = LEN_ - 1;
    const float* zp = z + (size_t)b * LEN_ * D_ + d;
    float s = 0.f;
    #pragma unroll 5
    for (int t = t0; t <= t1; t++) s += zp[(size_t)t * D_] * g_dts[t - 1];
    g_part[((size_t)b * NCHUNK_ + c) * D_ + d] = s;
}

// ---- chunked cumsum: phase 2 write X ----
__global__ void cumsum_write_kernel(const float* __restrict__ z) {
    int g = blockIdx.x * blockDim.x + threadIdx.x;
    int d = g & 15, c = (g >> 4) & (NCHUNK_ - 1), b = g >> 7;
    float acc = 0.f;
    for (int cc = 0; cc < c; cc++)
        acc += g_part[((size_t)b * NCHUNK_ + cc) * D_ + d];
    int t0 = c * 125 + 1;
    int t1 = (c + 1) * 125; if (t1 > LEN_ - 1) t1 = LEN_ - 1;
    const float* zp = z + (size_t)b * LEN_ * D_ + d;
    float* xp = g_X + (size_t)b * LEN_ * D_ + d;
    if (c == 0) xp[0] = 0.f;
    #pragma unroll 5
    for (int t = t0; t <= t1; t++) {
        acc += zp[(size_t)t * D_] * g_dts[t - 1];
        xp[(size_t)t * D_] = acc;
    }
}

__global__ void logsig_kernel() {
    int kk = blockIdx.x, b = blockIdx.y, tid = threadIdx.x;
    if (kk == 0) {
        if (tid < LOGSIG_) g_ls[(size_t)b * LOGSIG_ + tid] = 0.f;
        return;
    }
    int k = kk - 1, t1 = g_tidx[k], s0 = g_sidx[k];
    int nrow = t1 - s0 + 1;                          // <= 50
    __shared__ float sX[50 * 16];
    const float* xb = g_X + ((size_t)b * LEN_ + s0) * D_;
    for (int e = tid; e < (nrow * D_) >> 2; e += blockDim.x)
        reinterpret_cast<float4*>(sX)[e] = reinterpret_cast<const float4*>(xb)[e];
    __syncthreads();
    float* outp = g_ls + ((size_t)kk * B_ + b) * LOGSIG_;
    if (tid < D_) {
        outp[tid] = sX[(t1 - s0) * D_ + tid];
    } else if (tid < LOGSIG_) {
        int p = tid - D_, iu = g_iu[p], ju = g_ju[p];
        float xi = sX[iu], xj = sX[ju];
        float acc = 0.f;
        for (int s = 1; s < nrow; s++) {
            float yi = sX[s * D_ + iu], yj = sX[s * D_ + ju];
            acc += xi * (yj - xj) - xj * (yi - xi);
            xi = yi; xj = yj;
        }
        outp[tid] = 0.5f * acc;
    }
}

// ---- cp.async helpers ----
__device__ __forceinline__ void stage_chunk(const float* __restrict__ Wg, int Ktrue,
                                            int k0, float* sWbuf, int tid) {
    #pragma unroll
    for (int u = 0; u < 8; u++) {
        int g = (u << 8) + tid;
        int row = g >> 3;
        int k = k0 + ((g & 7) << 2);
        uint32_t dst = (uint32_t)__cvta_generic_to_shared(sWbuf + row * 36 + ((g & 7) << 2));
        bool valid = (k + 4 <= Ktrue);
        const float* src = valid ? (Wg + (size_t)row * Ktrue + k) : Wg;
        int sz = valid ? 16 : 0;
        asm volatile("cp.async.cg.shared.global [%0], [%1], 16, %2;"
                     :: "r"(dst), "l"(src), "r"(sz));
    }
    asm volatile("cp.async.commit_group;");
}

__device__ __forceinline__ void ffma2(unsigned long long& acc,
                                      unsigned long long a, unsigned long long b) {
    asm("fma.rn.f32x2 %0, %1, %2, %0;" : "+l"(acc) : "l"(a), "l"(b));
}

// GEMM: one output j = tid per thread, 8 batch rows; FFMA2 k-paired;
// double-buffered cp.async W staging. sW = base of 2 x WTILE_ buffers.
__device__ __forceinline__ void gemm8(
    const float* __restrict__ Wg, int Ktrue, int nch,
    const float* __restrict__ sin, int sstride,
    float* __restrict__ sW, int tid, float outv[BT_])
{
    unsigned long long acc[BT_];
    #pragma unroll
    for (int r = 0; r < BT_; r++) acc[r] = 0ULL;

    stage_chunk(Wg, Ktrue, 0, sW, tid);
    for (int ch = 0; ch < nch; ch++) {
        if (ch + 1 < nch) {
            stage_chunk(Wg, Ktrue, (ch + 1) << 5, sW + ((ch + 1) & 1) * WTILE_, tid);
            asm volatile("cp.async.wait_group 1;");
        } else {
            asm volatile("cp.async.wait_group 0;");
        }
        __syncthreads();
        const float* cur = sW + (ch & 1) * WTILE_;
        const int k0 = ch << 5;
        #pragma unroll
        for (int cg = 0; cg < 8; cg++) {
            ulonglong2 wv = *reinterpret_cast<const ulonglong2*>(cur + tid * 36 + (cg << 2));
            #pragma unroll
            for (int r = 0; r < BT_; r++) {
                ulonglong2 xv = *reinterpret_cast<const ulonglong2*>(
                    sin + r * sstride + k0 + (cg << 2));
                ffma2(acc[r], wv.x, xv.x);
                ffma2(acc[r], wv.y, xv.y);
            }
        }
        __syncthreads();
    }
    #pragma unroll
    for (int r = 0; r < BT_; r++) {
        float lo = __uint_as_float((unsigned)acc[r]);
        float hi = __uint_as_float((unsigned)(acc[r] >> 32));
        outv[r] = lo + hi;
    }
}

// One launch = one constant-last_h segment; CTA = 8 rows, full 4-layer MLP.
__global__ void __launch_bounds__(256, 2)
rnn_round_kernel(const float* __restrict__ W1, const float* __restrict__ b1,
                 const float* __restrict__ W2, const float* __restrict__ b2,
                 const float* __restrict__ W3, const float* __restrict__ b3,
                 const float* __restrict__ Wl, float* __restrict__ out,
                 int parity, int step0, int seglen)
{
    extern __shared__ float smem[];
    float* sW  = smem;                      // 2 * 256*36
    float* sIn = sW + 2 * WTILE_;           // BT*416 (reused for h)
    float* sA  = sIn + BT_ * K1P_;          // BT*256
    float* sB  = sA + BT_ * HID_;           // BT*256

    const float* last_in  = g_last[parity];
    float*       last_out = g_last[parity ^ 1];

    const int tid  = threadIdx.x;
    const int base = blockIdx.x * BT_;
    const int step = step0 + (base >> 9);
    const int b0   = base & 511;
    const bool is_last = (step == step0 + seglen - 1);

    for (int r = 0; r < BT_; r++) {
        int b = b0 + r;
        for (int c = tid; c < K1P_; c += 256) {
            float v = 0.f;
            if (c < HID_)     v = last_in[(size_t)b * HID_ + c];
            else if (c < K1_) v = g_ls[((size_t)step * B_ + b) * LOGSIG_ + (c - HID_)];
            sIn[r * K1P_ + c] = v;
        }
    }

    float v[BT_];

    gemm8(W1, K1_, K1P_ / 32, sIn, K1P_, sW, tid, v);
    {
        float bb = b1[tid];
        #pragma unroll
        for (int r = 0; r < BT_; r++)
            sA[r * HID_ + tid] = fmaxf(v[r] + bb, 0.f);
    }

    gemm8(W2, HID_, HID_ / 32, sA, HID_, sW, tid, v);
    {
        float bb = b2[tid];
        #pragma unroll
        for (int r = 0; r < BT_; r++)
            sB[r * HID_ + tid] = fmaxf(v[r] + bb, 0.f);
    }

    float* sH = sIn;   // reuse
    gemm8(W3, HID_, HID_ / 32, sB, HID_, sW, tid, v);
    {
        float bb = b3[tid];
        #pragma unroll
        for (int r = 0; r < BT_; r++) {
            float h = tanhf(v[r] + bb);
            sH[r * HID_ + tid] = h;
            if (is_last) last_out[(size_t)(b0 + r) * HID_ + tid] = h;
        }
    }
    __syncthreads();   // sH writes complete before layer-4 reads (stride changed)

    gemm8(Wl, HID_, HID_ / 32, sH, HID_, sW, tid, v);
    #pragma unroll
    for (int r = 0; r < BT_; r++) {
        int b = b0 + r;
        out[((size_t)b * WIN_ + step) * HID_ + tid] = v[r];
    }
}

// Replicate the reference's upd schedule -> segments (exact double math).
static void host_segments(int* seg_start, int* seg_len, int* nseg) {
    double tu[20];
    for (int j = 0; j < 20; j++) tu[j] = tb_d(50 * j);
    int u_idx[63];
    for (int k = 1; k < 64; k++) {
        double t = tt_d(k);
        int uj = 0;
        for (int j = 0; j < 20; j++) if (tu[j] <= t) uj = j;
        u_idx[k - 1] = uj;
    }
    double qt[64]; int qn = 0, last = -1;
    for (int k = 0; k < 63; k++) {
        int iu = u_idx[k] < 0 ? 0 : u_idx[k];
        if (iu != last) { qt[qn++] = tu[iu]; last = iu; }
    }
    qt[qn++] = tt_d(63);
    bool upd[64]; int qh = 0;
    for (int i = 0; i < 64; i++) {
        upd[i] = false;
        if (qh < qn && tt_d(i) >= qt[qh]) { qh++; upd[i] = true; }
    }
    *nseg = 0; int start = 0;
    for (int i = 0; i < 64; i++) {
        if (upd[i]) { seg_start[*nseg] = start; seg_len[*nseg] = i - start + 1; (*nseg)++; start = i + 1; }
    }
    if (start < 64) { seg_start[*nseg] = start; seg_len[*nseg] = 64 - start; (*nseg)++; }
}

extern "C" void kernel_launch(void* const* d_in, const int* in_sizes, int n_in,
                              void* d_out, int out_size) {
    (void)in_sizes; (void)n_in; (void)out_size;
    const float* z  = (const float*)d_in[0];
    const float* W1 = (const float*)d_in[1];
    const float* b1 = (const float*)d_in[2];
    const float* W2 = (const float*)d_in[3];
    const float* b2 = (const float*)d_in[4];
    const float* W3 = (const float*)d_in[5];
    const float* b3 = (const float*)d_in[6];
    const float* Wl = (const float*)d_in[7];
    float* out = (float*)d_out;

    const size_t smem_bytes =
        (2 * WTILE_ + BT_ * K1P_ + 2 * BT_ * HID_) * sizeof(float);   // ~103.4 KB
    cudaFuncSetAttribute(rnn_round_kernel,
                         cudaFuncAttributeMaxDynamicSharedMemorySize,
                         (int)smem_bytes);

    sched_kernel<<<1, 256>>>();
    zero_last_kernel<<<(B_ * HID_ + 255) / 256, 256>>>();
    cumsum_part_kernel<<<(B_ * NCHUNK_ * D_) / 256, 256>>>(z);
    cumsum_write_kernel<<<(B_ * NCHUNK_ * D_) / 256, 256>>>(z);
    logsig_kernel<<<dim3(WIN_, B_), 160>>>();

    int seg_start[64], seg_len[64], nseg = 0;
    host_segments(seg_start, seg_len, &nseg);

    int parity = 0;
    for (int s = 0; s < nseg; s++) {
        int grid = seg_len[s] * (B_ / BT_);
        rnn_round_kernel<<<grid, 256, smem_bytes>>>(
            W1, b1, W2, b2, W3, b3, Wl, out, parity, seg_start[s], seg_len[s]);
        parity ^= 1;
    }
}

// round 6
// speedup vs baseline: 1.4600x; 1.2859x over previous
#include <cuda_runtime.h>
#include <math.h>
#include <stdint.h>

constexpr int B_    = 512;
constexpr int LEN_  = 1000;
constexpr int D_    = 16;
constexpr int HID_  = 256;
constexpr int WIN_  = 64;
constexpr int PAIRS_  = 120;
constexpr int LOGSIG_ = 136;
constexpr int K1_   = HID_ + LOGSIG_;   // 392
constexpr int K1P_  = 416;              // 13*32
constexpr int BT_   = 16;               // batch rows per CTA
constexpr int NCHUNK_ = 16;             // cumsum time chunks
constexpr int WT_   = 256 * 32;         // swizzled W tile floats (8192)

__device__ float g_X[(size_t)B_ * LEN_ * D_];
__device__ float g_ls[(size_t)WIN_ * B_ * LOGSIG_];
__device__ float g_last[2][(size_t)B_ * HID_];
__device__ float g_part[(size_t)B_ * NCHUNK_ * D_];
__device__ float g_dts[LEN_ - 1];
__device__ int   g_tidx[WIN_ - 1];
__device__ int   g_sidx[WIN_ - 1];
__device__ int   g_iu[PAIRS_];
__device__ int   g_ju[PAIRS_];

__host__ __device__ __forceinline__ double tb_d(int i) {
    return (i == LEN_ - 1) ? 1.0 : (double)i * (1.0 / 999.0);
}
__host__ __device__ __forceinline__ double tt_d(int k) {
    return (k == WIN_ - 1) ? 1.0 : (double)k * (1.0 / 63.0);
}

__global__ void sched_kernel() {
    int tid = threadIdx.x;
    for (int i = tid; i < LEN_ - 1; i += blockDim.x)
        g_dts[i] = sqrtf((float)(tb_d(i + 1) - tb_d(i)));
    if (tid < WIN_ - 1) {
        double t = tt_d(tid + 1);
        int ti = 0;
        for (int i = 0; i < LEN_; i++) if (tb_d(i) <= t) ti = i;
        g_tidx[tid] = ti;
        int uj = 0;
        for (int j = 0; j < LEN_ / 50; j++) if (tb_d(50 * j) <= t) uj = j;
        g_sidx[tid] = 50 * uj;
    }
    if (tid >= 64 && tid < 64 + PAIRS_) {
        int p = tid - 64;
        int i = 0, accp = 0;
        while (accp + (D_ - 1 - i) <= p) { accp += D_ - 1 - i; i++; }
        g_iu[p] = i;
        g_ju[p] = i + 1 + (p - accp);
    }
}

__global__ void zero_last_kernel() {
    int g = blockIdx.x * blockDim.x + threadIdx.x;
    if (g < B_ * HID_) g_last[0][g] = 0.f;
}

// chunk c covers t in [c*63+1, min((c+1)*63, 999)]
__device__ __forceinline__ void chunk_rng(int c, int& t0, int& t1) {
    t0 = c * 63 + 1;
    t1 = (c + 1) * 63; if (t1 > LEN_ - 1) t1 = LEN_ - 1;
}

__global__ void cumsum_part_kernel(const float* __restrict__ z) {
    int g = blockIdx.x * blockDim.x + threadIdx.x;   // B*NCHUNK*D
    int d = g & 15, c = (g >> 4) & (NCHUNK_ - 1), b = g >> 8;
    int t0, t1; chunk_rng(c, t0, t1);
    const float* zp = z + (size_t)b * LEN_ * D_ + d;
    float s = 0.f;
    #pragma unroll 7
    for (int t = t0; t <= t1; t++) s += zp[(size_t)t * D_] * g_dts[t - 1];
    g_part[((size_t)b * NCHUNK_ + c) * D_ + d] = s;
}

__global__ void cumsum_write_kernel(const float* __restrict__ z) {
    int g = blockIdx.x * blockDim.x + threadIdx.x;
    int d = g & 15, c = (g >> 4) & (NCHUNK_ - 1), b = g >> 8;
    float acc = 0.f;
    for (int cc = 0; cc < c; cc++)
        acc += g_part[((size_t)b * NCHUNK_ + cc) * D_ + d];
    int t0, t1; chunk_rng(c, t0, t1);
    const float* zp = z + (size_t)b * LEN_ * D_ + d;
    float* xp = g_X + (size_t)b * LEN_ * D_ + d;
    if (c == 0) xp[0] = 0.f;
    #pragma unroll 7
    for (int t = t0; t <= t1; t++) {
        acc += zp[(size_t)t * D_] * g_dts[t - 1];
        xp[(size_t)t * D_] = acc;
    }
}

__global__ void logsig_kernel() {
    int kk = blockIdx.x, b = blockIdx.y, tid = threadIdx.x;
    if (kk == 0) {
        if (tid < LOGSIG_) g_ls[(size_t)b * LOGSIG_ + tid] = 0.f;
        return;
    }
    int k = kk - 1, t1 = g_tidx[k], s0 = g_sidx[k];
    int nrow = t1 - s0 + 1;                          // <= 50
    __shared__ float sX[50 * 16];
    const float* xb = g_X + ((size_t)b * LEN_ + s0) * D_;
    for (int e = tid; e < (nrow * D_) >> 2; e += blockDim.x)
        reinterpret_cast<float4*>(sX)[e] = reinterpret_cast<const float4*>(xb)[e];
    __syncthreads();
    float* outp = g_ls + ((size_t)kk * B_ + b) * LOGSIG_;
    if (tid < D_) {
        outp[tid] = sX[(t1 - s0) * D_ + tid];
    } else if (tid < LOGSIG_) {
        int p = tid - D_, iu = g_iu[p], ju = g_ju[p];
        float xi = sX[iu], xj = sX[ju];
        float acc = 0.f;
        for (int s = 1; s < nrow; s++) {
            float yi = sX[s * D_ + iu], yj = sX[s * D_ + ju];
            acc += xi * (yj - xj) - xj * (yi - xi);
            xi = yi; xj = yj;
        }
        outp[tid] = 0.5f * acc;
    }
}

// ---- stage one 256x32 W chunk, XOR-swizzled (float4 col ^= row&7) ----
__device__ __forceinline__ void stage_chunk(const float* __restrict__ Wg, int Ktrue,
                                            int k0, float* sWbuf, int tid) {
    #pragma unroll
    for (int u = 0; u < 8; u++) {
        int g = (u << 8) + tid;
        int row = g >> 3;
        int c4  = g & 7;
        int k   = k0 + (c4 << 2);
        uint32_t dst = (uint32_t)__cvta_generic_to_shared(
            sWbuf + row * 32 + ((c4 ^ (row & 7)) << 2));
        bool valid = (k + 4 <= Ktrue);
        const float* src = valid ? (Wg + (size_t)row * Ktrue + k) : Wg;
        int sz = valid ? 16 : 0;
        asm volatile("cp.async.cg.shared.global [%0], [%1], 16, %2;"
                     :: "r"(dst), "l"(src), "r"(sz));
    }
    asm volatile("cp.async.commit_group;");
}

__device__ __forceinline__ void ffma2(unsigned long long& acc,
                                      unsigned long long a, unsigned long long b) {
    asm("fma.rn.f32x2 %0, %1, %2, %0;" : "+l"(acc) : "l"(a), "l"(b));
}

// GEMM: thread (jt = tid&63, rg = tid>>6) computes j in {jt+64q} x 4 rows.
// x tile loaded lane-distinct once per chunk, distributed via shfl (static lanes).
__device__ __forceinline__ void gemm44(
    const float* __restrict__ Wg, int Ktrue, int nch,
    const float* __restrict__ sin, int sstride,
    float* __restrict__ sW, int tid, float outv[4][4])
{
    const int jt = tid & 63;
    const int rg = tid >> 6;
    const int lane = tid & 31;

    unsigned long long acc[4][4];
    #pragma unroll
    for (int q = 0; q < 4; q++)
        #pragma unroll
        for (int r = 0; r < 4; r++) acc[q][r] = 0ULL;

    stage_chunk(Wg, Ktrue, 0, sW, tid);
    for (int ch = 0; ch < nch; ch++) {
        if (ch + 1 < nch) {
            stage_chunk(Wg, Ktrue, (ch + 1) << 5, sW + ((ch + 1) & 1) * WT_, tid);
            asm volatile("cp.async.wait_group 1;");
        } else {
            asm volatile("cp.async.wait_group 0;");
        }
        __syncthreads();
        const float* cur = sW + (ch & 1) * WT_;
        const int k0 = ch << 5;

        // warp x-tile: lane l holds x[rg*4 + (l>>3)][k0 + (l&7)*4 .. +3]
        ulonglong2 xs = *reinterpret_cast<const ulonglong2*>(
            sin + (rg * 4 + (lane >> 3)) * sstride + k0 + ((lane & 7) << 2));

        #pragma unroll
        for (int c4 = 0; c4 < 8; c4++) {
            ulonglong2 wv[4];
            #pragma unroll
            for (int q = 0; q < 4; q++) {
                int row = jt + (q << 6);
                wv[q] = *reinterpret_cast<const ulonglong2*>(
                    cur + row * 32 + ((c4 ^ (row & 7)) << 2));
            }
            #pragma unroll
            for (int rr = 0; rr < 4; rr++) {
                const int src = (rr << 3) + c4;   // compile-time lane
                unsigned long long xa = __shfl_sync(0xffffffffu, xs.x, src);
                unsigned long long xb = __shfl_sync(0xffffffffu, xs.y, src);
                #pragma unroll
                for (int q = 0; q < 4; q++) {
                    ffma2(acc[q][rr], wv[q].x, xa);
                    ffma2(acc[q][rr], wv[q].y, xb);
                }
            }
        }
        __syncthreads();
    }
    #pragma unroll
    for (int q = 0; q < 4; q++)
        #pragma unroll
        for (int r = 0; r < 4; r++) {
            float lo = __uint_as_float((unsigned)acc[q][r]);
            float hi = __uint_as_float((unsigned)(acc[q][r] >> 32));
            outv[q][r] = lo + hi;
        }
}

// One launch = one constant-last_h segment; CTA = 16 rows, full 4-layer MLP.
__global__ void __launch_bounds__(256, 2)
rnn_round_kernel(const float* __restrict__ W1, const float* __restrict__ b1,
                 const float* __restrict__ W2, const float* __restrict__ b2,
                 const float* __restrict__ W3, const float* __restrict__ b3,
                 const float* __restrict__ Wl, float* __restrict__ out,
                 int parity, int step0, int seglen)
{
    extern __shared__ float smem[];
    float* sW = smem;                       // 2 * 256*32 swizzled
    float* R0 = sW + 2 * WT_;               // 16*416 (sIn, later sB)
    float* R1 = R0 + BT_ * K1P_;            // 16*256 (sA, later sH)

    const float* last_in  = g_last[parity];
    float*       last_out = g_last[parity ^ 1];

    const int tid  = threadIdx.x;
    const int jt   = tid & 63;
    const int rg   = tid >> 6;
    const int base = blockIdx.x * BT_;
    const int step = step0 + (base >> 9);
    const int b0   = base & 511;
    const bool is_last = (step == step0 + seglen - 1);

    // stage concat(last_h, logsig) -> R0 rows of 416 (zero pad 392..415)
    for (int r = 0; r < BT_; r++) {
        int b = b0 + r;
        for (int c = tid; c < K1P_; c += 256) {
            float v = 0.f;
            if (c < HID_)     v = last_in[(size_t)b * HID_ + c];
            else if (c < K1_) v = g_ls[((size_t)step * B_ + b) * LOGSIG_ + (c - HID_)];
            R0[r * K1P_ + c] = v;
        }
    }

    float v[4][4];

    gemm44(W1, K1_, K1P_ / 32, R0, K1P_, sW, tid, v);
    #pragma unroll
    for (int q = 0; q < 4; q++) {
        int j = jt + (q << 6); float bb = b1[j];
        #pragma unroll
        for (int rr = 0; rr < 4; rr++)
            R1[(rg * 4 + rr) * HID_ + j] = fmaxf(v[q][rr] + bb, 0.f);
    }
    __syncthreads();

    gemm44(W2, HID_, HID_ / 32, R1, HID_, sW, tid, v);
    __syncthreads();                       // R1 reads done before... (R0 write next)
    #pragma unroll
    for (int q = 0; q < 4; q++) {
        int j = jt + (q << 6); float bb = b2[j];
        #pragma unroll
        for (int rr = 0; rr < 4; rr++)
            R0[(rg * 4 + rr) * HID_ + j] = fmaxf(v[q][rr] + bb, 0.f);
    }
    __syncthreads();

    gemm44(W3, HID_, HID_ / 32, R0, HID_, sW, tid, v);
    __syncthreads();
    #pragma unroll
    for (int q = 0; q < 4; q++) {
        int j = jt + (q << 6); float bb = b3[j];
        #pragma unroll
        for (int rr = 0; rr < 4; rr++) {
            float h = tanhf(v[q][rr] + bb);
            R1[(rg * 4 + rr) * HID_ + j] = h;
            if (is_last) last_out[(size_t)(b0 + rg * 4 + rr) * HID_ + j] = h;
        }
    }
    __syncthreads();

    gemm44(Wl, HID_, HID_ / 32, R1, HID_, sW, tid, v);
    #pragma unroll
    for (int q = 0; q < 4; q++) {
        int j = jt + (q << 6);
        #pragma unroll
        for (int rr = 0; rr < 4; rr++) {
            int b = b0 + rg * 4 + rr;
            out[((size_t)b * WIN_ + step) * HID_ + j] = v[q][rr];
        }
    }
}

// Replicate the reference's upd schedule -> segments (exact double math).
static void host_segments(int* seg_start, int* seg_len, int* nseg) {
    double tu[20];
    for (int j = 0; j < 20; j++) tu[j] = tb_d(50 * j);
    int u_idx[63];
    for (int k = 1; k < 64; k++) {
        double t = tt_d(k);
        int uj = 0;
        for (int j = 0; j < 20; j++) if (tu[j] <= t) uj = j;
        u_idx[k - 1] = uj;
    }
    double qt[64]; int qn = 0, last = -1;
    for (int k = 0; k < 63; k++) {
        int iu = u_idx[k] < 0 ? 0 : u_idx[k];
        if (iu != last) { qt[qn++] = tu[iu]; last = iu; }
    }
    qt[qn++] = tt_d(63);
    bool upd[64]; int qh = 0;
    for (int i = 0; i < 64; i++) {
        upd[i] = false;
        if (qh < qn && tt_d(i) >= qt[qh]) { qh++; upd[i] = true; }
    }
    *nseg = 0; int start = 0;
    for (int i = 0; i < 64; i++) {
        if (upd[i]) { seg_start[*nseg] = start; seg_len[*nseg] = i - start + 1; (*nseg)++; start = i + 1; }
    }
    if (start < 64) { seg_start[*nseg] = start; seg_len[*nseg] = 64 - start; (*nseg)++; }
}

extern "C" void kernel_launch(void* const* d_in, const int* in_sizes, int n_in,
                              void* d_out, int out_size) {
    (void)in_sizes; (void)n_in; (void)out_size;
    const float* z  = (const float*)d_in[0];
    const float* W1 = (const float*)d_in[1];
    const float* b1 = (const float*)d_in[2];
    const float* W2 = (const float*)d_in[3];
    const float* b2 = (const float*)d_in[4];
    const float* W3 = (const float*)d_in[5];
    const float* b3 = (const float*)d_in[6];
    const float* Wl = (const float*)d_in[7];
    float* out = (float*)d_out;

    const size_t smem_bytes =
        (2 * WT_ + BT_ * K1P_ + BT_ * HID_) * sizeof(float);   // 106 KB
    cudaFuncSetAttribute(rnn_round_kernel,
                         cudaFuncAttributeMaxDynamicSharedMemorySize,
                         (int)smem_bytes);

    sched_kernel<<<1, 256>>>();
    zero_last_kernel<<<(B_ * HID_ + 255) / 256, 256>>>();
    cumsum_part_kernel<<<(B_ * NCHUNK_ * D_) / 256, 256>>>(z);
    cumsum_write_kernel<<<(B_ * NCHUNK_ * D_) / 256, 256>>>(z);
    logsig_kernel<<<dim3(WIN_, B_), 160>>>();

    int seg_start[64], seg_len[64], nseg = 0;
    host_segments(seg_start, seg_len, &nseg);

    int parity = 0;
    for (int s = 0; s < nseg; s++) {
        int grid = seg_len[s] * (B_ / BT_);
        rnn_round_kernel<<<grid, 256, smem_bytes>>>(
            W1, b1, W2, b2, W3, b3, Wl, out, parity, seg_start[s], seg_len[s]);
        parity ^= 1;
    }
}